// round 1
// baseline (speedup 1.0000x reference)
#include <cuda_runtime.h>
#include <cuda_bf16.h>
#include <math.h>

#define B 8
#define N 56
#define HW 3136           // 56*56
#define TOK 25088         // 8*56*56
#define EMBED 192
#define D1 576
#define TWO_N 112
#define RPE_H 32

// ---------------- device scratch ----------------
__device__ float g_p[TOK * D1];
__device__ float g_qv[TOK * D1];
__device__ float g_t[TOK * D1];
__device__ float g_a[2 * TWO_N * D1];   // a1 then a2
__device__ float g_h[2 * TWO_N * RPE_H];

__device__ __forceinline__ float silu_f(float x) { return x / (1.0f + expf(-x)); }

// ---------------- kernel A1: RPE hidden layers ----------------
__global__ void rpe_hidden_kernel(const float* __restrict__ w0a, const float* __restrict__ b0a,
                                  const float* __restrict__ wsa, const float* __restrict__ bsa,
                                  const float* __restrict__ w0b, const float* __restrict__ b0b,
                                  const float* __restrict__ wsb, const float* __restrict__ bsb) {
    int t = threadIdx.x;
    int tno = t >> 7;       // 0 or 1
    int row = t & 127;
    if (row >= TWO_N) return;
    const float* W0 = tno ? w0b : w0a;
    const float* B0 = tno ? b0b : b0a;
    const float* WS = tno ? wsb : wsa;
    const float* BS = tno ? bsb : bsa;

    float tv;
    if (row == 0 || row == 56) tv = 0.0f;
    else if (row < 56) tv = (float)row;
    else tv = -(float)(row - 56);

    float h[RPE_H];
#pragma unroll
    for (int j = 0; j < RPE_H; j++) h[j] = tv * W0[j] + B0[j];

    for (int L = 0; L < 3; L++) {
        float hn[RPE_H];
#pragma unroll
        for (int j = 0; j < RPE_H; j++) {
            float s = BS[L * RPE_H + j];
#pragma unroll
            for (int k = 0; k < RPE_H; k++)
                s += fmaxf(h[k], 0.0f) * WS[L * RPE_H * RPE_H + j * RPE_H + k];
            hn[j] = s;
        }
#pragma unroll
        for (int j = 0; j < RPE_H; j++) h[j] = hn[j];
    }
#pragma unroll
    for (int k = 0; k < RPE_H; k++)
        g_h[(tno * TWO_N + row) * RPE_H + k] = fmaxf(h[k], 0.0f);
}

// ---------------- kernel A2: RPE output layer * decay ----------------
__global__ void rpe_out_kernel(const float* __restrict__ wo1, const float* __restrict__ bo1,
                               const float* __restrict__ wo2, const float* __restrict__ bo2,
                               const float* __restrict__ slope) {
    int bx = blockIdx.x;            // 0..223
    int tno = bx / TWO_N;
    int row = bx % TWO_N;
    const float* WO = tno ? wo2 : wo1;
    const float* BO = tno ? bo2 : bo1;

    __shared__ float hs[RPE_H];
    if (threadIdx.x < RPE_H)
        hs[threadIdx.x] = g_h[(tno * TWO_N + row) * RPE_H + threadIdx.x];
    __syncthreads();

    int e;
    if (row == 0 || row == 56) e = 0;
    else if (row < 56) e = row;
    else e = TWO_N - row;

    for (int d = threadIdx.x; d < D1; d += blockDim.x) {
        float s = BO[d];
#pragma unroll
        for (int k = 0; k < RPE_H; k++) s += hs[k] * WO[d * RPE_H + k];
        float sl = slope[d];
        sl = fminf(fmaxf(sl, 0.0f), 1.0f);
        sl = 0.95f + 0.05f * sl;
        float dec = (e == 0) ? 1.0f : powf(sl, (float)e);
        g_a[(tno * TWO_N + row) * D1 + d] = s * dec;
    }
}

// ---------------- kernel B: fused p / q*v GEMMs ----------------
// C[m,n]: m over 25088 tokens, n over 576 channels, K=192.
// BM=128, BN=64, BK=16, 256 threads, 8x4 micro-tile, 3 output matrices.
__global__ __launch_bounds__(256) void pqv_kernel(
    const float* __restrict__ x,
    const float* __restrict__ pw, const float* __restrict__ pb,
    const float* __restrict__ qw, const float* __restrict__ qb,
    const float* __restrict__ vw, const float* __restrict__ vb) {
    __shared__ float As[16][132];
    __shared__ float Bp[16][64];
    __shared__ float Bq[16][64];
    __shared__ float Bv[16][64];

    int tid = threadIdx.x;
    int tx = tid & 15, ty = tid >> 4;
    int m0 = blockIdx.y * 128, n0 = blockIdx.x * 64;

    int ar = tid >> 1, ac = (tid & 1) * 8;     // A tile load: 128 rows x 16 cols
    int bn = tid >> 2, bk = (tid & 3) * 4;     // B tile load: 64 rows x 16 cols

    float acc[3][8][4];
#pragma unroll
    for (int mt = 0; mt < 3; mt++)
#pragma unroll
        for (int i = 0; i < 8; i++)
#pragma unroll
            for (int j = 0; j < 4; j++) acc[mt][i][j] = 0.0f;

    for (int kb = 0; kb < EMBED; kb += 16) {
        float4 a0 = *(const float4*)&x[(m0 + ar) * EMBED + kb + ac];
        float4 a1 = *(const float4*)&x[(m0 + ar) * EMBED + kb + ac + 4];
        As[ac + 0][ar] = a0.x; As[ac + 1][ar] = a0.y; As[ac + 2][ar] = a0.z; As[ac + 3][ar] = a0.w;
        As[ac + 4][ar] = a1.x; As[ac + 5][ar] = a1.y; As[ac + 6][ar] = a1.z; As[ac + 7][ar] = a1.w;

        float4 wp = *(const float4*)&pw[(n0 + bn) * EMBED + kb + bk];
        Bp[bk + 0][bn] = wp.x; Bp[bk + 1][bn] = wp.y; Bp[bk + 2][bn] = wp.z; Bp[bk + 3][bn] = wp.w;
        float4 wq = *(const float4*)&qw[(n0 + bn) * EMBED + kb + bk];
        Bq[bk + 0][bn] = wq.x; Bq[bk + 1][bn] = wq.y; Bq[bk + 2][bn] = wq.z; Bq[bk + 3][bn] = wq.w;
        float4 wv = *(const float4*)&vw[(n0 + bn) * EMBED + kb + bk];
        Bv[bk + 0][bn] = wv.x; Bv[bk + 1][bn] = wv.y; Bv[bk + 2][bn] = wv.z; Bv[bk + 3][bn] = wv.w;
        __syncthreads();

#pragma unroll
        for (int k = 0; k < 16; k++) {
            float av[8];
            float4 t0 = *(const float4*)&As[k][ty * 8];
            float4 t1 = *(const float4*)&As[k][ty * 8 + 4];
            av[0] = t0.x; av[1] = t0.y; av[2] = t0.z; av[3] = t0.w;
            av[4] = t1.x; av[5] = t1.y; av[6] = t1.z; av[7] = t1.w;
            float4 fp = *(const float4*)&Bp[k][tx * 4];
            float4 fq = *(const float4*)&Bq[k][tx * 4];
            float4 fv = *(const float4*)&Bv[k][tx * 4];
            float bpv[4] = {fp.x, fp.y, fp.z, fp.w};
            float bqv[4] = {fq.x, fq.y, fq.z, fq.w};
            float bvv[4] = {fv.x, fv.y, fv.z, fv.w};
#pragma unroll
            for (int i = 0; i < 8; i++) {
#pragma unroll
                for (int j = 0; j < 4; j++) {
                    acc[0][i][j] += av[i] * bpv[j];
                    acc[1][i][j] += av[i] * bqv[j];
                    acc[2][i][j] += av[i] * bvv[j];
                }
            }
        }
        __syncthreads();
    }

    // epilogue: p = silu(P), qv = silu(Q)*silu(V)
    int nbase = n0 + tx * 4;
    float pbv[4], qbv[4], vbv[4];
#pragma unroll
    for (int j = 0; j < 4; j++) { pbv[j] = pb[nbase + j]; qbv[j] = qb[nbase + j]; vbv[j] = vb[nbase + j]; }
#pragma unroll
    for (int i = 0; i < 8; i++) {
        int m = m0 + ty * 8 + i;
        float4 po, qo;
        float tmpp[4], tmpq[4];
#pragma unroll
        for (int j = 0; j < 4; j++) {
            tmpp[j] = silu_f(acc[0][i][j] + pbv[j]);
            tmpq[j] = silu_f(acc[1][i][j] + qbv[j]) * silu_f(acc[2][i][j] + vbv[j]);
        }
        po = make_float4(tmpp[0], tmpp[1], tmpp[2], tmpp[3]);
        qo = make_float4(tmpq[0], tmpq[1], tmpq[2], tmpq[3]);
        *(float4*)&g_p[m * D1 + nbase] = po;
        *(float4*)&g_qv[m * D1 + nbase] = qo;
    }
}

// ---------------- kernel C: axial Toeplitz + gate ----------------
// One block per (batch, 8-channel group). 512 threads: tid = (ti*8+tj)*8 + d.
// Each thread computes a 7x7 output tile for its channel d.
#define XPITCH 448   // 56*8 floats per grid row in smem
__global__ __launch_bounds__(512) void toeplitz_kernel() {
    extern __shared__ float sm[];
    float* Xs  = sm;                       // 56 * 448 = 25088 floats
    float* a1s = sm + N * XPITCH;          // 112*8
    float* a2s = a1s + TWO_N * 8;          // 112*8

    int dg = blockIdx.x;                    // 0..71
    int b  = blockIdx.y;                    // 0..7
    int dbase = dg * 8;
    int tid = threadIdx.x;

    // load qv slice: 3136 positions x 8 ch = 6272 float4s
    for (int idx = tid; idx < HW * 2; idx += 512) {
        int pos = idx >> 1;
        int q = (idx & 1) * 4;
        float4 v = *(const float4*)&g_qv[(b * HW + pos) * D1 + dbase + q];
        int i = pos / N, j = pos % N;
        *(float4*)&Xs[i * XPITCH + j * 8 + q] = v;
    }
    // load coefficients
    for (int idx = tid; idx < TWO_N * 8; idx += 512) {
        int row = idx >> 3, dd = idx & 7;
        a1s[idx] = g_a[row * D1 + dbase + dd];
        a2s[idx] = g_a[TWO_N * D1 + row * D1 + dbase + dd];
    }
    __syncthreads();

    int d  = tid & 7;
    int tp = tid >> 3;
    int tj = tp & 7;
    int ti = tp >> 3;
    int i0 = ti * 7, j0 = tj * 7;

    float acc[7][7];
#pragma unroll
    for (int ii = 0; ii < 7; ii++)
#pragma unroll
        for (int jj = 0; jj < 7; jj++) acc[ii][jj] = 0.0f;

    // o1: conv along width (j)
    for (int jp = 0; jp < N; jp++) {
        float xr[7];
#pragma unroll
        for (int ii = 0; ii < 7; ii++) xr[ii] = Xs[(i0 + ii) * XPITCH + jp * 8 + d];
        int base = j0 - jp;
        float ar[7];
#pragma unroll
        for (int jj = 0; jj < 7; jj++) {
            int l = base + jj;
            if (l < 0) l += TWO_N;
            ar[jj] = a1s[l * 8 + d];
        }
#pragma unroll
        for (int ii = 0; ii < 7; ii++)
#pragma unroll
            for (int jj = 0; jj < 7; jj++) acc[ii][jj] += xr[ii] * ar[jj];
    }
    // o2: conv along height (i)
    for (int ip = 0; ip < N; ip++) {
        float xc[7];
#pragma unroll
        for (int jj = 0; jj < 7; jj++) xc[jj] = Xs[ip * XPITCH + (j0 + jj) * 8 + d];
        int base = i0 - ip;
        float ar[7];
#pragma unroll
        for (int ii = 0; ii < 7; ii++) {
            int l = base + ii;
            if (l < 0) l += TWO_N;
            ar[ii] = a2s[l * 8 + d];
        }
#pragma unroll
        for (int ii = 0; ii < 7; ii++)
#pragma unroll
            for (int jj = 0; jj < 7; jj++) acc[ii][jj] += ar[ii] * xc[jj];
    }

    // epilogue: t = p * (o1 + o2)
#pragma unroll
    for (int ii = 0; ii < 7; ii++) {
        int i = i0 + ii;
#pragma unroll
        for (int jj = 0; jj < 7; jj++) {
            int j = j0 + jj;
            int gidx = (b * HW + i * N + j) * D1 + dbase + d;
            g_t[gidx] = g_p[gidx] * acc[ii][jj];
        }
    }
}

// ---------------- kernel D: output GEMM ----------------
// out[m, n] = sum_k t[m,k] * o_w[n,k] + o_b[n]; M=25088, N=192, K=576
__global__ __launch_bounds__(256) void out_gemm_kernel(
    const float* __restrict__ ow, const float* __restrict__ ob,
    float* __restrict__ out) {
    __shared__ float As[16][132];
    __shared__ float Bs[16][64];

    int tid = threadIdx.x;
    int tx = tid & 15, ty = tid >> 4;
    int m0 = blockIdx.y * 128, n0 = blockIdx.x * 64;
    int ar = tid >> 1, ac = (tid & 1) * 8;
    int bn = tid >> 2, bk = (tid & 3) * 4;

    float acc[8][4];
#pragma unroll
    for (int i = 0; i < 8; i++)
#pragma unroll
        for (int j = 0; j < 4; j++) acc[i][j] = 0.0f;

    for (int kb = 0; kb < D1; kb += 16) {
        float4 a0 = *(const float4*)&g_t[(m0 + ar) * D1 + kb + ac];
        float4 a1 = *(const float4*)&g_t[(m0 + ar) * D1 + kb + ac + 4];
        As[ac + 0][ar] = a0.x; As[ac + 1][ar] = a0.y; As[ac + 2][ar] = a0.z; As[ac + 3][ar] = a0.w;
        As[ac + 4][ar] = a1.x; As[ac + 5][ar] = a1.y; As[ac + 6][ar] = a1.z; As[ac + 7][ar] = a1.w;
        float4 wv = *(const float4*)&ow[(n0 + bn) * D1 + kb + bk];
        Bs[bk + 0][bn] = wv.x; Bs[bk + 1][bn] = wv.y; Bs[bk + 2][bn] = wv.z; Bs[bk + 3][bn] = wv.w;
        __syncthreads();

#pragma unroll
        for (int k = 0; k < 16; k++) {
            float av[8];
            float4 t0 = *(const float4*)&As[k][ty * 8];
            float4 t1 = *(const float4*)&As[k][ty * 8 + 4];
            av[0] = t0.x; av[1] = t0.y; av[2] = t0.z; av[3] = t0.w;
            av[4] = t1.x; av[5] = t1.y; av[6] = t1.z; av[7] = t1.w;
            float4 fb = *(const float4*)&Bs[k][tx * 4];
            float bv[4] = {fb.x, fb.y, fb.z, fb.w};
#pragma unroll
            for (int i = 0; i < 8; i++)
#pragma unroll
                for (int j = 0; j < 4; j++) acc[i][j] += av[i] * bv[j];
        }
        __syncthreads();
    }

    int nbase = n0 + tx * 4;
    float obv[4];
#pragma unroll
    for (int j = 0; j < 4; j++) obv[j] = ob[nbase + j];
#pragma unroll
    for (int i = 0; i < 8; i++) {
        int m = m0 + ty * 8 + i;
        float4 o = make_float4(acc[i][0] + obv[0], acc[i][1] + obv[1],
                               acc[i][2] + obv[2], acc[i][3] + obv[3]);
        *(float4*)&out[m * EMBED + nbase] = o;
    }
}

// ---------------- launch ----------------
extern "C" void kernel_launch(void* const* d_in, const int* in_sizes, int n_in,
                              void* d_out, int out_size) {
    const float* x    = (const float*)d_in[0];
    const float* p_w  = (const float*)d_in[1];
    const float* p_b  = (const float*)d_in[2];
    const float* q_w  = (const float*)d_in[3];
    const float* q_b  = (const float*)d_in[4];
    const float* v_w  = (const float*)d_in[5];
    const float* v_b  = (const float*)d_in[6];
    const float* o_w  = (const float*)d_in[7];
    const float* o_b  = (const float*)d_in[8];
    const float* slope = (const float*)d_in[9];
    const float* t1_w0 = (const float*)d_in[10];
    const float* t1_b0 = (const float*)d_in[11];
    const float* t1_ws = (const float*)d_in[12];
    const float* t1_bs = (const float*)d_in[13];
    const float* t1_wo = (const float*)d_in[14];
    const float* t1_bo = (const float*)d_in[15];
    const float* t2_w0 = (const float*)d_in[16];
    const float* t2_b0 = (const float*)d_in[17];
    const float* t2_ws = (const float*)d_in[18];
    const float* t2_bs = (const float*)d_in[19];
    const float* t2_wo = (const float*)d_in[20];
    const float* t2_bo = (const float*)d_in[21];
    float* out = (float*)d_out;

    // Toeplitz kernel needs 105KB dynamic smem
    static const int smemC = (N * XPITCH + 2 * TWO_N * 8) * (int)sizeof(float);
    cudaFuncSetAttribute(toeplitz_kernel, cudaFuncAttributeMaxDynamicSharedMemorySize, smemC);

    rpe_hidden_kernel<<<1, 256>>>(t1_w0, t1_b0, t1_ws, t1_bs, t2_w0, t2_b0, t2_ws, t2_bs);
    rpe_out_kernel<<<2 * TWO_N, 128>>>(t1_wo, t1_bo, t2_wo, t2_bo, slope);
    pqv_kernel<<<dim3(D1 / 64, TOK / 128), 256>>>(x, p_w, p_b, q_w, q_b, v_w, v_b);
    toeplitz_kernel<<<dim3(D1 / 8, B), 512, smemC>>>();
    out_gemm_kernel<<<dim3(EMBED / 64, TOK / 128), 256>>>(o_w, o_b, out);
}

// round 3
// speedup vs baseline: 1.3901x; 1.3901x over previous
#include <cuda_runtime.h>
#include <cuda_bf16.h>
#include <math.h>
#include <stdint.h>

#define B 8
#define N 56
#define HW 3136           // 56*56
#define TOK 25088         // 8*56*56
#define EMBED 192
#define D1 576
#define TWO_N 112
#define RPE_H 32

// ---------------- device scratch ----------------
__device__ float g_p[TOK * D1];
__device__ float g_qv[TOK * D1];
__device__ float g_t[TOK * D1];
__device__ float g_a[2 * TWO_N * D1];   // a1 then a2
__device__ float g_h[2 * TWO_N * RPE_H];

__device__ __forceinline__ float silu_f(float x) { return x / (1.0f + expf(-x)); }

__device__ __forceinline__ uint32_t to_tf32(float x) {
    uint32_t r;
    asm("cvt.rna.tf32.f32 %0, %1;" : "=r"(r) : "f"(x));
    return r;
}

__device__ __forceinline__ void mma_tf32(float c[4], const uint32_t a[4], const uint32_t b[2]) {
    asm volatile(
        "mma.sync.aligned.m16n8k8.row.col.f32.tf32.tf32.f32 "
        "{%0,%1,%2,%3}, {%4,%5,%6,%7}, {%8,%9}, {%0,%1,%2,%3};"
        : "+f"(c[0]), "+f"(c[1]), "+f"(c[2]), "+f"(c[3])
        : "r"(a[0]), "r"(a[1]), "r"(a[2]), "r"(a[3]), "r"(b[0]), "r"(b[1]));
}

// ---------------- kernel A1: RPE hidden layers ----------------
__global__ void rpe_hidden_kernel(const float* __restrict__ w0a, const float* __restrict__ b0a,
                                  const float* __restrict__ wsa, const float* __restrict__ bsa,
                                  const float* __restrict__ w0b, const float* __restrict__ b0b,
                                  const float* __restrict__ wsb, const float* __restrict__ bsb) {
    int t = threadIdx.x;
    int tno = t >> 7;       // 0 or 1
    int row = t & 127;
    if (row >= TWO_N) return;
    const float* W0 = tno ? w0b : w0a;
    const float* B0 = tno ? b0b : b0a;
    const float* WS = tno ? wsb : wsa;
    const float* BS = tno ? bsb : bsa;

    float tv;
    if (row == 0 || row == 56) tv = 0.0f;
    else if (row < 56) tv = (float)row;
    else tv = -(float)(row - 56);

    float h[RPE_H];
#pragma unroll
    for (int j = 0; j < RPE_H; j++) h[j] = tv * W0[j] + B0[j];

    for (int L = 0; L < 3; L++) {
        float hn[RPE_H];
#pragma unroll
        for (int j = 0; j < RPE_H; j++) {
            float s = BS[L * RPE_H + j];
#pragma unroll
            for (int k = 0; k < RPE_H; k++)
                s += fmaxf(h[k], 0.0f) * WS[L * RPE_H * RPE_H + j * RPE_H + k];
            hn[j] = s;
        }
#pragma unroll
        for (int j = 0; j < RPE_H; j++) h[j] = hn[j];
    }
#pragma unroll
    for (int k = 0; k < RPE_H; k++)
        g_h[(tno * TWO_N + row) * RPE_H + k] = fmaxf(h[k], 0.0f);
}

// ---------------- kernel A2: RPE output layer * decay ----------------
__global__ void rpe_out_kernel(const float* __restrict__ wo1, const float* __restrict__ bo1,
                               const float* __restrict__ wo2, const float* __restrict__ bo2,
                               const float* __restrict__ slope) {
    int bx = blockIdx.x;            // 0..223
    int tno = bx / TWO_N;
    int row = bx % TWO_N;
    const float* WO = tno ? wo2 : wo1;
    const float* BO = tno ? bo2 : bo1;

    __shared__ float hs[RPE_H];
    if (threadIdx.x < RPE_H)
        hs[threadIdx.x] = g_h[(tno * TWO_N + row) * RPE_H + threadIdx.x];
    __syncthreads();

    int e;
    if (row == 0 || row == 56) e = 0;
    else if (row < 56) e = row;
    else e = TWO_N - row;

    for (int d = threadIdx.x; d < D1; d += blockDim.x) {
        float s = BO[d];
#pragma unroll
        for (int k = 0; k < RPE_H; k++) s += hs[k] * WO[d * RPE_H + k];
        float sl = slope[d];
        sl = fminf(fmaxf(sl, 0.0f), 1.0f);
        sl = 0.95f + 0.05f * sl;
        float dec = (e == 0) ? 1.0f : powf(sl, (float)e);
        g_a[(tno * TWO_N + row) * D1 + d] = s * dec;
    }
}

// ---------------- kernel B: fused p / q*v GEMMs (TF32 mma) ----------------
// C[m,n]: m over 25088 tokens, n over 576 channels, K=192. 3 output mats.
// BM=128, BN=64, BK=32. 256 threads = 8 warps in 4(m) x 2(n); warp tile 32x32.
#define APITCH 136   // ≡ 8 mod 32 -> conflict-free frag loads
#define BPITCH 72    // ≡ 8 mod 32
__global__ __launch_bounds__(256, 1) void pqv_kernel(
    const float* __restrict__ x,
    const float* __restrict__ pw, const float* __restrict__ pb,
    const float* __restrict__ qw, const float* __restrict__ qb,
    const float* __restrict__ vw, const float* __restrict__ vb) {
    __shared__ float As[32][APITCH];          // [k][m], tf32 bits
    __shared__ float Bs[3][32][BPITCH];       // [mat][k][n], tf32 bits

    int tid = threadIdx.x;
    int warp = tid >> 5, lane = tid & 31;
    int wm = (warp >> 1) * 32;                // warp m offset within block
    int wn = (warp & 1) * 32;                 // warp n offset within block
    int quad = lane >> 2, tid4 = lane & 3;
    int m0 = blockIdx.y * 128, n0 = blockIdx.x * 64;

    // loader indices
    int lrow = tid >> 1;                      // 0..127 (A row)
    int lcb  = (tid & 1) * 16;                // A col base (16 floats)
    int wrow = tid >> 2;                      // 0..63 (B row = n)
    int wkb  = (tid & 3) * 8;                 // B col base (8 floats)

    const float* wmats[3] = {pw, qw, vw};

    float c[3][2][4][4];
#pragma unroll
    for (int mt2 = 0; mt2 < 3; mt2++)
#pragma unroll
        for (int i = 0; i < 2; i++)
#pragma unroll
            for (int j = 0; j < 4; j++)
#pragma unroll
                for (int r = 0; r < 4; r++) c[mt2][i][j][r] = 0.0f;

    for (int kb = 0; kb < EMBED; kb += 32) {
        // load A tile 128x32 (transposed to [k][m]) with tf32 cvt
#pragma unroll
        for (int v = 0; v < 4; v++) {
            float4 a = *(const float4*)&x[(m0 + lrow) * EMBED + kb + lcb + v * 4];
            As[lcb + v * 4 + 0][lrow] = __uint_as_float(to_tf32(a.x));
            As[lcb + v * 4 + 1][lrow] = __uint_as_float(to_tf32(a.y));
            As[lcb + v * 4 + 2][lrow] = __uint_as_float(to_tf32(a.z));
            As[lcb + v * 4 + 3][lrow] = __uint_as_float(to_tf32(a.w));
        }
        // load 3 weight tiles 64x32 -> [k][n]
#pragma unroll
        for (int mat = 0; mat < 3; mat++) {
            const float* W = wmats[mat];
            float4 w0 = *(const float4*)&W[(n0 + wrow) * EMBED + kb + wkb];
            float4 w1 = *(const float4*)&W[(n0 + wrow) * EMBED + kb + wkb + 4];
            Bs[mat][wkb + 0][wrow] = __uint_as_float(to_tf32(w0.x));
            Bs[mat][wkb + 1][wrow] = __uint_as_float(to_tf32(w0.y));
            Bs[mat][wkb + 2][wrow] = __uint_as_float(to_tf32(w0.z));
            Bs[mat][wkb + 3][wrow] = __uint_as_float(to_tf32(w0.w));
            Bs[mat][wkb + 4][wrow] = __uint_as_float(to_tf32(w1.x));
            Bs[mat][wkb + 5][wrow] = __uint_as_float(to_tf32(w1.y));
            Bs[mat][wkb + 6][wrow] = __uint_as_float(to_tf32(w1.z));
            Bs[mat][wkb + 7][wrow] = __uint_as_float(to_tf32(w1.w));
        }
        __syncthreads();

#pragma unroll
        for (int k8 = 0; k8 < 32; k8 += 8) {
            uint32_t a[2][4];
#pragma unroll
            for (int mt = 0; mt < 2; mt++) {
                int mb = wm + mt * 16;
                a[mt][0] = __float_as_uint(As[k8 + tid4][mb + quad]);
                a[mt][1] = __float_as_uint(As[k8 + tid4][mb + quad + 8]);
                a[mt][2] = __float_as_uint(As[k8 + tid4 + 4][mb + quad]);
                a[mt][3] = __float_as_uint(As[k8 + tid4 + 4][mb + quad + 8]);
            }
#pragma unroll
            for (int mat = 0; mat < 3; mat++) {
#pragma unroll
                for (int nt = 0; nt < 4; nt++) {
                    uint32_t b[2];
                    int nb = wn + nt * 8 + quad;
                    b[0] = __float_as_uint(Bs[mat][k8 + tid4][nb]);
                    b[1] = __float_as_uint(Bs[mat][k8 + tid4 + 4][nb]);
#pragma unroll
                    for (int mt = 0; mt < 2; mt++)
                        mma_tf32(c[mat][mt][nt], a[mt], b);
                }
            }
        }
        __syncthreads();
    }

    // epilogue: p = silu(P), qv = silu(Q)*silu(V)
#pragma unroll
    for (int mt = 0; mt < 2; mt++) {
#pragma unroll
        for (int half = 0; half < 2; half++) {   // c regs 0,1 (row quad) / 2,3 (row quad+8)
            int m = m0 + wm + mt * 16 + quad + half * 8;
#pragma unroll
            for (int nt = 0; nt < 4; nt++) {
                int n = n0 + wn + nt * 8 + tid4 * 2;
                float cp0 = c[0][mt][nt][half * 2 + 0] + pb[n];
                float cp1 = c[0][mt][nt][half * 2 + 1] + pb[n + 1];
                float cq0 = c[1][mt][nt][half * 2 + 0] + qb[n];
                float cq1 = c[1][mt][nt][half * 2 + 1] + qb[n + 1];
                float cv0 = c[2][mt][nt][half * 2 + 0] + vb[n];
                float cv1 = c[2][mt][nt][half * 2 + 1] + vb[n + 1];
                float2 pv = make_float2(silu_f(cp0), silu_f(cp1));
                float2 qv = make_float2(silu_f(cq0) * silu_f(cv0),
                                        silu_f(cq1) * silu_f(cv1));
                *(float2*)&g_p[m * D1 + n] = pv;
                *(float2*)&g_qv[m * D1 + n] = qv;
            }
        }
    }
}

// ---------------- kernel C: axial Toeplitz + gate ----------------
#define XPITCH 448   // 56*8 floats per grid row in smem
__global__ __launch_bounds__(512) void toeplitz_kernel() {
    extern __shared__ float sm[];
    float* Xs  = sm;                       // 56 * 448 = 25088 floats
    float* a1s = sm + N * XPITCH;          // 112*8
    float* a2s = a1s + TWO_N * 8;          // 112*8

    int dg = blockIdx.x;                    // 0..71
    int b  = blockIdx.y;                    // 0..7
    int dbase = dg * 8;
    int tid = threadIdx.x;

    for (int idx = tid; idx < HW * 2; idx += 512) {
        int pos = idx >> 1;
        int q = (idx & 1) * 4;
        float4 v = *(const float4*)&g_qv[(b * HW + pos) * D1 + dbase + q];
        int i = pos / N, j = pos % N;
        *(float4*)&Xs[i * XPITCH + j * 8 + q] = v;
    }
    for (int idx = tid; idx < TWO_N * 8; idx += 512) {
        int row = idx >> 3, dd = idx & 7;
        a1s[idx] = g_a[row * D1 + dbase + dd];
        a2s[idx] = g_a[TWO_N * D1 + row * D1 + dbase + dd];
    }
    __syncthreads();

    int d  = tid & 7;
    int tp = tid >> 3;
    int tj = tp & 7;
    int ti = tp >> 3;
    int i0 = ti * 7, j0 = tj * 7;

    float acc[7][7];
#pragma unroll
    for (int ii = 0; ii < 7; ii++)
#pragma unroll
        for (int jj = 0; jj < 7; jj++) acc[ii][jj] = 0.0f;

    for (int jp = 0; jp < N; jp++) {
        float xr[7];
#pragma unroll
        for (int ii = 0; ii < 7; ii++) xr[ii] = Xs[(i0 + ii) * XPITCH + jp * 8 + d];
        int base = j0 - jp;
        float ar[7];
#pragma unroll
        for (int jj = 0; jj < 7; jj++) {
            int l = base + jj;
            if (l < 0) l += TWO_N;
            ar[jj] = a1s[l * 8 + d];
        }
#pragma unroll
        for (int ii = 0; ii < 7; ii++)
#pragma unroll
            for (int jj = 0; jj < 7; jj++) acc[ii][jj] += xr[ii] * ar[jj];
    }
    for (int ip = 0; ip < N; ip++) {
        float xc[7];
#pragma unroll
        for (int jj = 0; jj < 7; jj++) xc[jj] = Xs[ip * XPITCH + (j0 + jj) * 8 + d];
        int base = i0 - ip;
        float ar[7];
#pragma unroll
        for (int ii = 0; ii < 7; ii++) {
            int l = base + ii;
            if (l < 0) l += TWO_N;
            ar[ii] = a2s[l * 8 + d];
        }
#pragma unroll
        for (int ii = 0; ii < 7; ii++)
#pragma unroll
            for (int jj = 0; jj < 7; jj++) acc[ii][jj] += ar[ii] * xc[jj];
    }

#pragma unroll
    for (int ii = 0; ii < 7; ii++) {
        int i = i0 + ii;
#pragma unroll
        for (int jj = 0; jj < 7; jj++) {
            int j = j0 + jj;
            int gidx = (b * HW + i * N + j) * D1 + dbase + d;
            g_t[gidx] = g_p[gidx] * acc[ii][jj];
        }
    }
}

// ---------------- kernel D: output GEMM (TF32 mma) ----------------
// out[m, n] = sum_k t[m,k] * o_w[n,k] + o_b[n]; M=25088, N=192, K=576
__global__ __launch_bounds__(256, 1) void out_gemm_kernel(
    const float* __restrict__ ow, const float* __restrict__ ob,
    float* __restrict__ out) {
    __shared__ float As[32][APITCH];
    __shared__ float Bs[32][BPITCH];

    int tid = threadIdx.x;
    int warp = tid >> 5, lane = tid & 31;
    int wm = (warp >> 1) * 32;
    int wn = (warp & 1) * 32;
    int quad = lane >> 2, tid4 = lane & 3;
    int m0 = blockIdx.y * 128, n0 = blockIdx.x * 64;

    int lrow = tid >> 1;
    int lcb  = (tid & 1) * 16;
    int wrow = tid >> 2;
    int wkb  = (tid & 3) * 8;

    float c[2][4][4];
#pragma unroll
    for (int i = 0; i < 2; i++)
#pragma unroll
        for (int j = 0; j < 4; j++)
#pragma unroll
            for (int r = 0; r < 4; r++) c[i][j][r] = 0.0f;

    for (int kb = 0; kb < D1; kb += 32) {
#pragma unroll
        for (int v = 0; v < 4; v++) {
            float4 a = *(const float4*)&g_t[(m0 + lrow) * D1 + kb + lcb + v * 4];
            As[lcb + v * 4 + 0][lrow] = __uint_as_float(to_tf32(a.x));
            As[lcb + v * 4 + 1][lrow] = __uint_as_float(to_tf32(a.y));
            As[lcb + v * 4 + 2][lrow] = __uint_as_float(to_tf32(a.z));
            As[lcb + v * 4 + 3][lrow] = __uint_as_float(to_tf32(a.w));
        }
        {
            float4 w0 = *(const float4*)&ow[(n0 + wrow) * D1 + kb + wkb];
            float4 w1 = *(const float4*)&ow[(n0 + wrow) * D1 + kb + wkb + 4];
            Bs[wkb + 0][wrow] = __uint_as_float(to_tf32(w0.x));
            Bs[wkb + 1][wrow] = __uint_as_float(to_tf32(w0.y));
            Bs[wkb + 2][wrow] = __uint_as_float(to_tf32(w0.z));
            Bs[wkb + 3][wrow] = __uint_as_float(to_tf32(w0.w));
            Bs[wkb + 4][wrow] = __uint_as_float(to_tf32(w1.x));
            Bs[wkb + 5][wrow] = __uint_as_float(to_tf32(w1.y));
            Bs[wkb + 6][wrow] = __uint_as_float(to_tf32(w1.z));
            Bs[wkb + 7][wrow] = __uint_as_float(to_tf32(w1.w));
        }
        __syncthreads();

#pragma unroll
        for (int k8 = 0; k8 < 32; k8 += 8) {
            uint32_t a[2][4];
#pragma unroll
            for (int mt = 0; mt < 2; mt++) {
                int mb = wm + mt * 16;
                a[mt][0] = __float_as_uint(As[k8 + tid4][mb + quad]);
                a[mt][1] = __float_as_uint(As[k8 + tid4][mb + quad + 8]);
                a[mt][2] = __float_as_uint(As[k8 + tid4 + 4][mb + quad]);
                a[mt][3] = __float_as_uint(As[k8 + tid4 + 4][mb + quad + 8]);
            }
#pragma unroll
            for (int nt = 0; nt < 4; nt++) {
                uint32_t b[2];
                int nb = wn + nt * 8 + quad;
                b[0] = __float_as_uint(Bs[k8 + tid4][nb]);
                b[1] = __float_as_uint(Bs[k8 + tid4 + 4][nb]);
#pragma unroll
                for (int mt = 0; mt < 2; mt++)
                    mma_tf32(c[mt][nt], a[mt], b);
            }
        }
        __syncthreads();
    }

#pragma unroll
    for (int mt = 0; mt < 2; mt++) {
#pragma unroll
        for (int half = 0; half < 2; half++) {
            int m = m0 + wm + mt * 16 + quad + half * 8;
#pragma unroll
            for (int nt = 0; nt < 4; nt++) {
                int n = n0 + wn + nt * 8 + tid4 * 2;
                float2 o = make_float2(c[mt][nt][half * 2 + 0] + ob[n],
                                       c[mt][nt][half * 2 + 1] + ob[n + 1]);
                *(float2*)&out[m * EMBED + n] = o;
            }
        }
    }
}

// ---------------- launch ----------------
extern "C" void kernel_launch(void* const* d_in, const int* in_sizes, int n_in,
                              void* d_out, int out_size) {
    const float* x    = (const float*)d_in[0];
    const float* p_w  = (const float*)d_in[1];
    const float* p_b  = (const float*)d_in[2];
    const float* q_w  = (const float*)d_in[3];
    const float* q_b  = (const float*)d_in[4];
    const float* v_w  = (const float*)d_in[5];
    const float* v_b  = (const float*)d_in[6];
    const float* o_w  = (const float*)d_in[7];
    const float* o_b  = (const float*)d_in[8];
    const float* slope = (const float*)d_in[9];
    const float* t1_w0 = (const float*)d_in[10];
    const float* t1_b0 = (const float*)d_in[11];
    const float* t1_ws = (const float*)d_in[12];
    const float* t1_bs = (const float*)d_in[13];
    const float* t1_wo = (const float*)d_in[14];
    const float* t1_bo = (const float*)d_in[15];
    const float* t2_w0 = (const float*)d_in[16];
    const float* t2_b0 = (const float*)d_in[17];
    const float* t2_ws = (const float*)d_in[18];
    const float* t2_bs = (const float*)d_in[19];
    const float* t2_wo = (const float*)d_in[20];
    const float* t2_bo = (const float*)d_in[21];
    float* out = (float*)d_out;

    static const int smemC = (N * XPITCH + 2 * TWO_N * 8) * (int)sizeof(float);
    cudaFuncSetAttribute(toeplitz_kernel, cudaFuncAttributeMaxDynamicSharedMemorySize, smemC);

    rpe_hidden_kernel<<<1, 256>>>(t1_w0, t1_b0, t1_ws, t1_bs, t2_w0, t2_b0, t2_ws, t2_bs);
    rpe_out_kernel<<<2 * TWO_N, 128>>>(t1_wo, t1_bo, t2_wo, t2_bo, slope);
    pqv_kernel<<<dim3(D1 / 64, TOK / 128), 256>>>(x, p_w, p_b, q_w, q_b, v_w, v_b);
    toeplitz_kernel<<<dim3(D1 / 8, B), 512, smemC>>>();
    out_gemm_kernel<<<dim3(EMBED / 64, TOK / 128), 256>>>(o_w, o_b, out);
}

// round 4
// speedup vs baseline: 1.4870x; 1.0697x over previous
#include <cuda_runtime.h>
#include <cuda_bf16.h>
#include <math.h>
#include <stdint.h>

#define B 8
#define N 56
#define HW 3136           // 56*56
#define TOK 25088         // 8*56*56
#define EMBED 192
#define D1 576
#define TWO_N 112
#define RPE_H 32

// ---------------- device scratch ----------------
__device__ float g_p[TOK * D1];
__device__ float g_qv[TOK * D1];
__device__ float g_t[TOK * D1];
__device__ float g_a[2 * TWO_N * D1];   // a1 then a2
__device__ float g_h[2 * TWO_N * RPE_H];

__device__ __forceinline__ float silu_f(float x) { return x / (1.0f + expf(-x)); }

__device__ __forceinline__ uint32_t to_tf32(float x) {
    uint32_t r;
    asm("cvt.rna.tf32.f32 %0, %1;" : "=r"(r) : "f"(x));
    return r;
}

__device__ __forceinline__ void mma_tf32(float c[4], const uint32_t a[4], const uint32_t b[2]) {
    asm volatile(
        "mma.sync.aligned.m16n8k8.row.col.f32.tf32.tf32.f32 "
        "{%0,%1,%2,%3}, {%4,%5,%6,%7}, {%8,%9}, {%0,%1,%2,%3};"
        : "+f"(c[0]), "+f"(c[1]), "+f"(c[2]), "+f"(c[3])
        : "r"(a[0]), "r"(a[1]), "r"(a[2]), "r"(a[3]), "r"(b[0]), "r"(b[1]));
}

// f32x2 packed helpers (sm_103a FFMA2 — PTX-only path)
__device__ __forceinline__ unsigned long long pk2(float lo, float hi) {
    unsigned long long r;
    asm("mov.b64 %0, {%1, %2};" : "=l"(r) : "f"(lo), "f"(hi));
    return r;
}
__device__ __forceinline__ void fma2(unsigned long long& c, unsigned long long a, unsigned long long b) {
    asm("fma.rn.f32x2 %0, %1, %2, %0;" : "+l"(c) : "l"(a), "l"(b));
}
__device__ __forceinline__ void unpk2(float& lo, float& hi, unsigned long long v) {
    asm("mov.b64 {%0, %1}, %2;" : "=f"(lo), "=f"(hi) : "l"(v));
}

// ---------------- kernel A1: RPE hidden layers ----------------
__global__ void rpe_hidden_kernel(const float* __restrict__ w0a, const float* __restrict__ b0a,
                                  const float* __restrict__ wsa, const float* __restrict__ bsa,
                                  const float* __restrict__ w0b, const float* __restrict__ b0b,
                                  const float* __restrict__ wsb, const float* __restrict__ bsb) {
    int t = threadIdx.x;
    int tno = t >> 7;       // 0 or 1
    int row = t & 127;
    if (row >= TWO_N) return;
    const float* W0 = tno ? w0b : w0a;
    const float* B0 = tno ? b0b : b0a;
    const float* WS = tno ? wsb : wsa;
    const float* BS = tno ? bsb : bsa;

    float tv;
    if (row == 0 || row == 56) tv = 0.0f;
    else if (row < 56) tv = (float)row;
    else tv = -(float)(row - 56);

    float h[RPE_H];
#pragma unroll
    for (int j = 0; j < RPE_H; j++) h[j] = tv * W0[j] + B0[j];

    for (int L = 0; L < 3; L++) {
        float hn[RPE_H];
#pragma unroll
        for (int j = 0; j < RPE_H; j++) {
            float s = BS[L * RPE_H + j];
#pragma unroll
            for (int k = 0; k < RPE_H; k++)
                s += fmaxf(h[k], 0.0f) * WS[L * RPE_H * RPE_H + j * RPE_H + k];
            hn[j] = s;
        }
#pragma unroll
        for (int j = 0; j < RPE_H; j++) h[j] = hn[j];
    }
#pragma unroll
    for (int k = 0; k < RPE_H; k++)
        g_h[(tno * TWO_N + row) * RPE_H + k] = fmaxf(h[k], 0.0f);
}

// ---------------- kernel A2: RPE output layer * decay ----------------
__global__ void rpe_out_kernel(const float* __restrict__ wo1, const float* __restrict__ bo1,
                               const float* __restrict__ wo2, const float* __restrict__ bo2,
                               const float* __restrict__ slope) {
    int bx = blockIdx.x;            // 0..223
    int tno = bx / TWO_N;
    int row = bx % TWO_N;
    const float* WO = tno ? wo2 : wo1;
    const float* BO = tno ? bo2 : bo1;

    __shared__ float hs[RPE_H];
    if (threadIdx.x < RPE_H)
        hs[threadIdx.x] = g_h[(tno * TWO_N + row) * RPE_H + threadIdx.x];
    __syncthreads();

    int e;
    if (row == 0 || row == 56) e = 0;
    else if (row < 56) e = row;
    else e = TWO_N - row;

    for (int d = threadIdx.x; d < D1; d += blockDim.x) {
        float s = BO[d];
#pragma unroll
        for (int k = 0; k < RPE_H; k++) s += hs[k] * WO[d * RPE_H + k];
        float sl = slope[d];
        sl = fminf(fmaxf(sl, 0.0f), 1.0f);
        sl = 0.95f + 0.05f * sl;
        float dec = (e == 0) ? 1.0f : powf(sl, (float)e);
        g_a[(tno * TWO_N + row) * D1 + d] = s * dec;
    }
}

// ---------------- kernel B: fused p / q*v GEMMs (TF32 mma) ----------------
#define APITCH 136   // ≡ 8 mod 32 -> conflict-free frag loads
#define BPITCH 72    // ≡ 8 mod 32
__global__ __launch_bounds__(256, 1) void pqv_kernel(
    const float* __restrict__ x,
    const float* __restrict__ pw, const float* __restrict__ pb,
    const float* __restrict__ qw, const float* __restrict__ qb,
    const float* __restrict__ vw, const float* __restrict__ vb) {
    __shared__ float As[32][APITCH];          // [k][m], tf32 bits
    __shared__ float Bs[3][32][BPITCH];       // [mat][k][n], tf32 bits

    int tid = threadIdx.x;
    int warp = tid >> 5, lane = tid & 31;
    int wm = (warp >> 1) * 32;
    int wn = (warp & 1) * 32;
    int quad = lane >> 2, tid4 = lane & 3;
    int m0 = blockIdx.y * 128, n0 = blockIdx.x * 64;

    int lrow = tid >> 1;
    int lcb  = (tid & 1) * 16;
    int wrow = tid >> 2;
    int wkb  = (tid & 3) * 8;

    const float* wmats[3] = {pw, qw, vw};

    float c[3][2][4][4];
#pragma unroll
    for (int mt2 = 0; mt2 < 3; mt2++)
#pragma unroll
        for (int i = 0; i < 2; i++)
#pragma unroll
            for (int j = 0; j < 4; j++)
#pragma unroll
                for (int r = 0; r < 4; r++) c[mt2][i][j][r] = 0.0f;

    for (int kb = 0; kb < EMBED; kb += 32) {
#pragma unroll
        for (int v = 0; v < 4; v++) {
            float4 a = *(const float4*)&x[(m0 + lrow) * EMBED + kb + lcb + v * 4];
            As[lcb + v * 4 + 0][lrow] = __uint_as_float(to_tf32(a.x));
            As[lcb + v * 4 + 1][lrow] = __uint_as_float(to_tf32(a.y));
            As[lcb + v * 4 + 2][lrow] = __uint_as_float(to_tf32(a.z));
            As[lcb + v * 4 + 3][lrow] = __uint_as_float(to_tf32(a.w));
        }
#pragma unroll
        for (int mat = 0; mat < 3; mat++) {
            const float* W = wmats[mat];
            float4 w0 = *(const float4*)&W[(n0 + wrow) * EMBED + kb + wkb];
            float4 w1 = *(const float4*)&W[(n0 + wrow) * EMBED + kb + wkb + 4];
            Bs[mat][wkb + 0][wrow] = __uint_as_float(to_tf32(w0.x));
            Bs[mat][wkb + 1][wrow] = __uint_as_float(to_tf32(w0.y));
            Bs[mat][wkb + 2][wrow] = __uint_as_float(to_tf32(w0.z));
            Bs[mat][wkb + 3][wrow] = __uint_as_float(to_tf32(w0.w));
            Bs[mat][wkb + 4][wrow] = __uint_as_float(to_tf32(w1.x));
            Bs[mat][wkb + 5][wrow] = __uint_as_float(to_tf32(w1.y));
            Bs[mat][wkb + 6][wrow] = __uint_as_float(to_tf32(w1.z));
            Bs[mat][wkb + 7][wrow] = __uint_as_float(to_tf32(w1.w));
        }
        __syncthreads();

#pragma unroll
        for (int k8 = 0; k8 < 32; k8 += 8) {
            uint32_t a[2][4];
#pragma unroll
            for (int mt = 0; mt < 2; mt++) {
                int mb = wm + mt * 16;
                a[mt][0] = __float_as_uint(As[k8 + tid4][mb + quad]);
                a[mt][1] = __float_as_uint(As[k8 + tid4][mb + quad + 8]);
                a[mt][2] = __float_as_uint(As[k8 + tid4 + 4][mb + quad]);
                a[mt][3] = __float_as_uint(As[k8 + tid4 + 4][mb + quad + 8]);
            }
#pragma unroll
            for (int mat = 0; mat < 3; mat++) {
#pragma unroll
                for (int nt = 0; nt < 4; nt++) {
                    uint32_t b[2];
                    int nb = wn + nt * 8 + quad;
                    b[0] = __float_as_uint(Bs[mat][k8 + tid4][nb]);
                    b[1] = __float_as_uint(Bs[mat][k8 + tid4 + 4][nb]);
#pragma unroll
                    for (int mt = 0; mt < 2; mt++)
                        mma_tf32(c[mat][mt][nt], a[mt], b);
                }
            }
        }
        __syncthreads();
    }

#pragma unroll
    for (int mt = 0; mt < 2; mt++) {
#pragma unroll
        for (int half = 0; half < 2; half++) {
            int m = m0 + wm + mt * 16 + quad + half * 8;
#pragma unroll
            for (int nt = 0; nt < 4; nt++) {
                int n = n0 + wn + nt * 8 + tid4 * 2;
                float cp0 = c[0][mt][nt][half * 2 + 0] + pb[n];
                float cp1 = c[0][mt][nt][half * 2 + 1] + pb[n + 1];
                float cq0 = c[1][mt][nt][half * 2 + 0] + qb[n];
                float cq1 = c[1][mt][nt][half * 2 + 1] + qb[n + 1];
                float cv0 = c[2][mt][nt][half * 2 + 0] + vb[n];
                float cv1 = c[2][mt][nt][half * 2 + 1] + vb[n + 1];
                float2 pv = make_float2(silu_f(cp0), silu_f(cp1));
                float2 qv = make_float2(silu_f(cq0) * silu_f(cv0),
                                        silu_f(cq1) * silu_f(cv1));
                *(float2*)&g_p[m * D1 + n] = pv;
                *(float2*)&g_qv[m * D1 + n] = qv;
            }
        }
    }
}

// ---------------- kernel C: axial Toeplitz + gate (f32x2 packed) ----------------
// One block per (batch, 8-channel group). 512 threads: tid = (ti*8+tj)*8 + d.
// Each thread computes a 7x7 output tile, packed as acc2[ii][p] with
// lane-lo = col 2p, lane-hi = col 2p+1 (col 7 = pad, discarded).
#define XPITCH 448   // 56*8 floats per grid row in smem
#define AELEN 112    // extended coeff array length (idx k -> lag (k-55) mod 112)
__global__ __launch_bounds__(512) void toeplitz_kernel() {
    extern __shared__ float sm[];
    float* Xs  = sm;                       // 56 * 448 = 25088 floats
    float* a1e = sm + N * XPITCH;          // 112*8
    float* a2e = a1e + AELEN * 8;          // 112*8

    int dg = blockIdx.x;                    // 0..71
    int b  = blockIdx.y;                    // 0..7
    int dbase = dg * 8;
    int tid = threadIdx.x;

    // load qv slice: 3136 positions x 8 ch
    for (int idx = tid; idx < HW * 2; idx += 512) {
        int pos = idx >> 1;
        int q = (idx & 1) * 4;
        float4 v = *(const float4*)&g_qv[(b * HW + pos) * D1 + dbase + q];
        int i = pos / N, j = pos % N;
        *(float4*)&Xs[i * XPITCH + j * 8 + q] = v;
    }
    // extended coefficients: a?e[k][d] = a?[(k-55) mod 112][d]
    for (int idx = tid; idx < AELEN * 8; idx += 512) {
        int k = idx >> 3, dd = idx & 7;
        int src = (k + 57) % TWO_N;
        a1e[idx] = g_a[src * D1 + dbase + dd];
        a2e[idx] = g_a[TWO_N * D1 + src * D1 + dbase + dd];
    }
    __syncthreads();

    int d  = tid & 7;
    int tp = tid >> 3;
    int tj = tp & 7;
    int ti = tp >> 3;
    int i0 = ti * 7, j0 = tj * 7;

    unsigned long long acc[7][4];
#pragma unroll
    for (int ii = 0; ii < 7; ii++)
#pragma unroll
        for (int p = 0; p < 4; p++) acc[ii][p] = 0ull;

    // ---- o1: conv along width (j). acc[ii][p] += x[ii] (dup) * (a[2p], a[2p+1])
    {
        const float* xp = &Xs[i0 * XPITCH + d];
        const float* ap = &a1e[(j0 + 55) * 8 + d];
#pragma unroll 4
        for (int jp = 0; jp < N; jp++) {
            unsigned long long xd[7];
#pragma unroll
            for (int ii = 0; ii < 7; ii++) {
                float xv = xp[ii * XPITCH];
                xd[ii] = pk2(xv, xv);
            }
            float av[8];
#pragma unroll
            for (int t = 0; t < 8; t++) av[t] = ap[t * 8];
            unsigned long long apk[4];
#pragma unroll
            for (int p = 0; p < 4; p++) apk[p] = pk2(av[2 * p], av[2 * p + 1]);
#pragma unroll
            for (int ii = 0; ii < 7; ii++)
#pragma unroll
                for (int p = 0; p < 4; p++) fma2(acc[ii][p], xd[ii], apk[p]);
            xp += 8;
            ap -= 8;
        }
    }
    // ---- o2: conv along height (i). acc[ii][p] += a[ii] (dup) * (x[2p], x[2p+1])
    {
        const float* xp = &Xs[j0 * 8 + d];
        const float* ap = &a2e[(i0 + 55) * 8 + d];
#pragma unroll 4
        for (int ip = 0; ip < N; ip++) {
            float xv[8];
#pragma unroll
            for (int t = 0; t < 8; t++) xv[t] = xp[t * 8];
            unsigned long long xpk[4];
#pragma unroll
            for (int p = 0; p < 4; p++) xpk[p] = pk2(xv[2 * p], xv[2 * p + 1]);
            unsigned long long ad[7];
#pragma unroll
            for (int ii = 0; ii < 7; ii++) {
                float a = ap[ii * 8];
                ad[ii] = pk2(a, a);
            }
#pragma unroll
            for (int ii = 0; ii < 7; ii++)
#pragma unroll
                for (int p = 0; p < 4; p++) fma2(acc[ii][p], ad[ii], xpk[p]);
            xp += XPITCH;
            ap -= 8;
        }
    }

    // epilogue: t = p * (o1 + o2)
#pragma unroll
    for (int ii = 0; ii < 7; ii++) {
        int i = i0 + ii;
        long base = (long)(b * HW + i * N + j0) * D1 + dbase + d;
#pragma unroll
        for (int p = 0; p < 4; p++) {
            float lo, hi;
            unpk2(lo, hi, acc[ii][p]);
            int jj = 2 * p;
            g_t[base + (long)jj * D1] = g_p[base + (long)jj * D1] * lo;
            if (jj + 1 < 7)
                g_t[base + (long)(jj + 1) * D1] = g_p[base + (long)(jj + 1) * D1] * hi;
        }
    }
}

// ---------------- kernel D: output GEMM (TF32 mma) ----------------
__global__ __launch_bounds__(256, 1) void out_gemm_kernel(
    const float* __restrict__ ow, const float* __restrict__ ob,
    float* __restrict__ out) {
    __shared__ float As[32][APITCH];
    __shared__ float Bs[32][BPITCH];

    int tid = threadIdx.x;
    int warp = tid >> 5, lane = tid & 31;
    int wm = (warp >> 1) * 32;
    int wn = (warp & 1) * 32;
    int quad = lane >> 2, tid4 = lane & 3;
    int m0 = blockIdx.y * 128, n0 = blockIdx.x * 64;

    int lrow = tid >> 1;
    int lcb  = (tid & 1) * 16;
    int wrow = tid >> 2;
    int wkb  = (tid & 3) * 8;

    float c[2][4][4];
#pragma unroll
    for (int i = 0; i < 2; i++)
#pragma unroll
        for (int j = 0; j < 4; j++)
#pragma unroll
            for (int r = 0; r < 4; r++) c[i][j][r] = 0.0f;

    for (int kb = 0; kb < D1; kb += 32) {
#pragma unroll
        for (int v = 0; v < 4; v++) {
            float4 a = *(const float4*)&g_t[(m0 + lrow) * D1 + kb + lcb + v * 4];
            As[lcb + v * 4 + 0][lrow] = __uint_as_float(to_tf32(a.x));
            As[lcb + v * 4 + 1][lrow] = __uint_as_float(to_tf32(a.y));
            As[lcb + v * 4 + 2][lrow] = __uint_as_float(to_tf32(a.z));
            As[lcb + v * 4 + 3][lrow] = __uint_as_float(to_tf32(a.w));
        }
        {
            float4 w0 = *(const float4*)&ow[(n0 + wrow) * D1 + kb + wkb];
            float4 w1 = *(const float4*)&ow[(n0 + wrow) * D1 + kb + wkb + 4];
            Bs[wkb + 0][wrow] = __uint_as_float(to_tf32(w0.x));
            Bs[wkb + 1][wrow] = __uint_as_float(to_tf32(w0.y));
            Bs[wkb + 2][wrow] = __uint_as_float(to_tf32(w0.z));
            Bs[wkb + 3][wrow] = __uint_as_float(to_tf32(w0.w));
            Bs[wkb + 4][wrow] = __uint_as_float(to_tf32(w1.x));
            Bs[wkb + 5][wrow] = __uint_as_float(to_tf32(w1.y));
            Bs[wkb + 6][wrow] = __uint_as_float(to_tf32(w1.z));
            Bs[wkb + 7][wrow] = __uint_as_float(to_tf32(w1.w));
        }
        __syncthreads();

#pragma unroll
        for (int k8 = 0; k8 < 32; k8 += 8) {
            uint32_t a[2][4];
#pragma unroll
            for (int mt = 0; mt < 2; mt++) {
                int mb = wm + mt * 16;
                a[mt][0] = __float_as_uint(As[k8 + tid4][mb + quad]);
                a[mt][1] = __float_as_uint(As[k8 + tid4][mb + quad + 8]);
                a[mt][2] = __float_as_uint(As[k8 + tid4 + 4][mb + quad]);
                a[mt][3] = __float_as_uint(As[k8 + tid4 + 4][mb + quad + 8]);
            }
#pragma unroll
            for (int nt = 0; nt < 4; nt++) {
                uint32_t b[2];
                int nb = wn + nt * 8 + quad;
                b[0] = __float_as_uint(Bs[k8 + tid4][nb]);
                b[1] = __float_as_uint(Bs[k8 + tid4 + 4][nb]);
#pragma unroll
                for (int mt = 0; mt < 2; mt++)
                    mma_tf32(c[mt][nt], a[mt], b);
            }
        }
        __syncthreads();
    }

#pragma unroll
    for (int mt = 0; mt < 2; mt++) {
#pragma unroll
        for (int half = 0; half < 2; half++) {
            int m = m0 + wm + mt * 16 + quad + half * 8;
#pragma unroll
            for (int nt = 0; nt < 4; nt++) {
                int n = n0 + wn + nt * 8 + tid4 * 2;
                float2 o = make_float2(c[mt][nt][half * 2 + 0] + ob[n],
                                       c[mt][nt][half * 2 + 1] + ob[n + 1]);
                *(float2*)&out[m * EMBED + n] = o;
            }
        }
    }
}

// ---------------- launch ----------------
extern "C" void kernel_launch(void* const* d_in, const int* in_sizes, int n_in,
                              void* d_out, int out_size) {
    const float* x    = (const float*)d_in[0];
    const float* p_w  = (const float*)d_in[1];
    const float* p_b  = (const float*)d_in[2];
    const float* q_w  = (const float*)d_in[3];
    const float* q_b  = (const float*)d_in[4];
    const float* v_w  = (const float*)d_in[5];
    const float* v_b  = (const float*)d_in[6];
    const float* o_w  = (const float*)d_in[7];
    const float* o_b  = (const float*)d_in[8];
    const float* slope = (const float*)d_in[9];
    const float* t1_w0 = (const float*)d_in[10];
    const float* t1_b0 = (const float*)d_in[11];
    const float* t1_ws = (const float*)d_in[12];
    const float* t1_bs = (const float*)d_in[13];
    const float* t1_wo = (const float*)d_in[14];
    const float* t1_bo = (const float*)d_in[15];
    const float* t2_w0 = (const float*)d_in[16];
    const float* t2_b0 = (const float*)d_in[17];
    const float* t2_ws = (const float*)d_in[18];
    const float* t2_bs = (const float*)d_in[19];
    const float* t2_wo = (const float*)d_in[20];
    const float* t2_bo = (const float*)d_in[21];
    float* out = (float*)d_out;

    static const int smemC = (N * XPITCH + 2 * AELEN * 8) * (int)sizeof(float);
    cudaFuncSetAttribute(toeplitz_kernel, cudaFuncAttributeMaxDynamicSharedMemorySize, smemC);

    rpe_hidden_kernel<<<1, 256>>>(t1_w0, t1_b0, t1_ws, t1_bs, t2_w0, t2_b0, t2_ws, t2_bs);
    rpe_out_kernel<<<2 * TWO_N, 128>>>(t1_wo, t1_bo, t2_wo, t2_bo, slope);
    pqv_kernel<<<dim3(D1 / 64, TOK / 128), 256>>>(x, p_w, p_b, q_w, q_b, v_w, v_b);
    toeplitz_kernel<<<dim3(D1 / 8, B), 512, smemC>>>();
    out_gemm_kernel<<<dim3(EMBED / 64, TOK / 128), 256>>>(o_w, o_b, out);
}